// round 13
// baseline (speedup 1.0000x reference)
#include <cuda_runtime.h>
#include <cuda_fp16.h>
#include <math_constants.h>
#include <cstdint>

#define BB 2
#define SS 2048
#define DDIM 1024
#define HH 16
#define HDIM 64
#define MM (BB*SS)          // 4096 rows
#define QKV_LD 3072         // 3*D

// ---------------------------------------------------------------------------
// Scratch (device globals: allowed; runtime allocs are not)
// ---------------------------------------------------------------------------
__device__ __half g_qkv[(size_t)MM * QKV_LD];    // QKV fp16 (Q pre-scaled)
__device__ __half g_xh[(size_t)MM * DDIM];       // x fp16
__device__ __half g_w1h[(size_t)QKV_LD * DDIM];  // w_attn^T fp16 [3072,1024]
__device__ __half g_w2h[(size_t)DDIM * DDIM];    // w_proj^T fp16 [1024,1024]
__device__ __half g_ah[(size_t)MM * DDIM];       // attention out fp16

// ---------------------------------------------------------------------------
// Portable PTX helpers
// ---------------------------------------------------------------------------
__device__ __forceinline__ uint32_t smem_u32(const void* p) {
    uint32_t a;
    asm("{ .reg .u64 t; cvta.to.shared.u64 t, %1; cvt.u32.u64 %0, t; }"
        : "=r"(a) : "l"(p));
    return a;
}

#define CP_ASYNC16(sa, gp) \
    asm volatile("cp.async.cg.shared.global [%0], [%1], 16;" :: "r"(sa), "l"(gp))
#define CP_COMMIT() asm volatile("cp.async.commit_group;" ::: "memory")
#define CP_WAIT2()  asm volatile("cp.async.wait_group 2;" ::: "memory")
#define CP_WAIT1()  asm volatile("cp.async.wait_group 1;" ::: "memory")
#define CP_WAIT0()  asm volatile("cp.async.wait_group 0;" ::: "memory")

#define LDSM_X4(r0, r1, r2, r3, addr) \
    asm volatile("ldmatrix.sync.aligned.m8n8.x4.shared.b16 {%0,%1,%2,%3}, [%4];" \
        : "=r"(r0), "=r"(r1), "=r"(r2), "=r"(r3) : "r"(addr))

#define LDSM_X4_T(r0, r1, r2, r3, addr) \
    asm volatile("ldmatrix.sync.aligned.m8n8.x4.trans.shared.b16 {%0,%1,%2,%3}, [%4];" \
        : "=r"(r0), "=r"(r1), "=r"(r2), "=r"(r3) : "r"(addr))

#define MMA_F16(c, a0, a1, a2, a3, b0, b1) \
    asm volatile("mma.sync.aligned.m16n8k16.row.col.f32.f16.f16.f32 " \
        "{%0,%1,%2,%3}, {%4,%5,%6,%7}, {%8,%9}, {%0,%1,%2,%3};" \
        : "+f"((c)[0]), "+f"((c)[1]), "+f"((c)[2]), "+f"((c)[3]) \
        : "r"(a0), "r"(a1), "r"(a2), "r"(a3), "r"(b0), "r"(b1))

__device__ __forceinline__ uint32_t pack_hf2(float a, float b) {
    __half2 t = __floats2half2_rn(a, b);
    return *(uint32_t*)&t;
}

// XOR swizzle for 128B rows (ch in 0..7): conflict-free per 8-lane phase.
__device__ __forceinline__ uint32_t sw128(uint32_t r, uint32_t ch) {
    return r * 128 + ((ch ^ (r & 7)) << 4);
}

// ---------------------------------------------------------------------------
// Fused prep: one launch does x->fp16 cast + both weight transposes.
// blocks [0,1024): split x; [1024,4096): w1^T; [4096,5120): w2^T.
// ---------------------------------------------------------------------------
__device__ __forceinline__ void transpose_body(const float* __restrict__ W,
                                               __half* __restrict__ hi,
                                               int K, int N, int bx, int by,
                                               int tid)
{
    __shared__ float t[32][33];
    int n0 = bx * 32, k0 = by * 32;
    int tx = tid & 31, ty = tid >> 5;
#pragma unroll
    for (int i = 0; i < 32; i += 8)
        t[ty + i][tx] = W[(size_t)(k0 + ty + i) * N + n0 + tx];
    __syncthreads();
#pragma unroll
    for (int i = 0; i < 32; i += 8)
        hi[(size_t)(n0 + ty + i) * K + k0 + tx] = __float2half(t[tx][ty + i]);
}

__global__ void prep_all(const float* __restrict__ x, __half* __restrict__ xh,
                         const float* __restrict__ w1, __half* __restrict__ w1h,
                         const float* __restrict__ w2, __half* __restrict__ w2h)
{
    const int bid = blockIdx.x, tid = threadIdx.x;
    if (bid < 1024) {
        const int n4 = MM * DDIM / 4;
        for (int i = bid * 256 + tid; i < n4; i += 1024 * 256) {
            float4 v = ((const float4*)x)[i];
            ((uint32_t*)xh)[2 * i]     = pack_hf2(v.x, v.y);
            ((uint32_t*)xh)[2 * i + 1] = pack_hf2(v.z, v.w);
        }
    } else if (bid < 4096) {
        int t = bid - 1024;                       // 96 x 32 blocks
        transpose_body(w1, w1h, DDIM, QKV_LD, t % 96, t / 96, tid);
    } else {
        int t = bid - 4096;                       // 32 x 32 blocks
        transpose_body(w2, w2h, DDIM, DDIM, t % 32, t / 32, tid);
    }
}

// ---------------------------------------------------------------------------
// HMMA fp16 GEMM + bias (fp32 accumulate): C = Ah @ Bh^T + bias
// R12 version (best measured): 128x128 CTA, 32x64 warp tile, K-tile 64,
// 3-stage cp.async, register double-buffered fragments.
// MODE 0: fp32 C.  MODE 1: fp16 C (Q cols scaled 0.125).
// ---------------------------------------------------------------------------
#define GARR 16384
#define GSTAGE (2 * GARR)            // 32768
#define HMMA_SMEM (3 * GSTAGE)       // 98304 -> 2 CTAs/SM

template<int MODE>
__global__ __launch_bounds__(256, 2)
void hmma_gemm(const __half* __restrict__ Ah, const __half* __restrict__ Bh,
               const float* __restrict__ bias, float* __restrict__ C,
               __half* __restrict__ Chi, int K, int N)
{
    extern __shared__ __align__(16) char smraw[];
    const uint32_t sb = smem_u32(smraw);

    const int tid = threadIdx.x;
    const int wid = tid >> 5, lane = tid & 31;
    const int m0 = blockIdx.y * 128, n0 = blockIdx.x * 128;
    const int warp_m = wid & 3;
    const int warp_n = wid >> 2;

    float c[2][8][4];
#pragma unroll
    for (int mi = 0; mi < 2; mi++)
#pragma unroll
        for (int nt = 0; nt < 8; nt++)
#pragma unroll
            for (int j = 0; j < 4; j++) c[mi][nt][j] = 0.f;

    const int nkt = K / 64;

    auto load_stage = [&](int kt, int slot) {
        const int k0 = kt * 64;
        const uint32_t sbase = sb + (uint32_t)slot * GSTAGE;
#pragma unroll
        for (int arr = 0; arr < 2; arr++) {
            const __half* P = (arr == 0) ? Ah : Bh;
            const int rowbase = (arr == 0) ? m0 : n0;
#pragma unroll
            for (int i = 0; i < 4; i++) {
                uint32_t idx = tid + i * 256;
                uint32_t r = idx >> 3, ch = idx & 7;
                const __half* gp = P + (size_t)(rowbase + r) * K + k0 + ch * 8;
                CP_ASYNC16(sbase + arr * GARR + sw128(r, ch), gp);
            }
        }
        CP_COMMIT();
    };

    load_stage(0, 0);
    load_stage(1, 1);

    const uint32_t lrow = lane & 15;
    const uint32_t lch  = lane >> 4;
    const uint32_t aRow = (uint32_t)(warp_m * 32) + lrow;
    const uint32_t bRow = (uint32_t)(warp_n * 64) + lrow;

    for (int kt = 0; kt < nkt; kt++) {
        if (kt + 2 < nkt) CP_WAIT1(); else CP_WAIT0();
        __syncthreads();
        if (kt + 2 < nkt) load_stage(kt + 2, (kt + 2) % 3);

        const uint32_t sbase = sb + (uint32_t)(kt % 3) * GSTAGE;

        uint32_t ah[2][2][4];   // [buf][mi][frag]
        uint32_t bh[2][4];      // [buf][frag]

        {
            const uint32_t ch = lch;
            LDSM_X4(ah[0][0][0], ah[0][0][1], ah[0][0][2], ah[0][0][3],
                    sbase + sw128(aRow, ch));
            LDSM_X4(ah[0][1][0], ah[0][1][1], ah[0][1][2], ah[0][1][3],
                    sbase + sw128(aRow + 16, ch));
            LDSM_X4(bh[0][0], bh[0][1], bh[0][2], bh[0][3],
                    sbase + GARR + sw128(bRow, ch));
        }

#pragma unroll
        for (int ks = 0; ks < 4; ks++) {
            const int ab = ks & 1;
#pragma unroll
            for (int np = 0; np < 4; np++) {
                const int bb = np & 1;
                if (np < 3) {
                    const uint32_t ch = ks * 2 + lch;
                    LDSM_X4(bh[bb ^ 1][0], bh[bb ^ 1][1], bh[bb ^ 1][2], bh[bb ^ 1][3],
                            sbase + GARR + sw128(bRow + (np + 1) * 16, ch));
                } else if (ks < 3) {
                    const uint32_t ch = (ks + 1) * 2 + lch;
                    LDSM_X4(ah[ab ^ 1][0][0], ah[ab ^ 1][0][1], ah[ab ^ 1][0][2], ah[ab ^ 1][0][3],
                            sbase + sw128(aRow, ch));
                    LDSM_X4(ah[ab ^ 1][1][0], ah[ab ^ 1][1][1], ah[ab ^ 1][1][2], ah[ab ^ 1][1][3],
                            sbase + sw128(aRow + 16, ch));
                    LDSM_X4(bh[bb ^ 1][0], bh[bb ^ 1][1], bh[bb ^ 1][2], bh[bb ^ 1][3],
                            sbase + GARR + sw128(bRow, ch));
                }
                const int n0t = np * 2, n1t = np * 2 + 1;
                MMA_F16(c[0][n0t], ah[ab][0][0], ah[ab][0][1], ah[ab][0][2], ah[ab][0][3],
                        bh[bb][0], bh[bb][2]);
                MMA_F16(c[0][n1t], ah[ab][0][0], ah[ab][0][1], ah[ab][0][2], ah[ab][0][3],
                        bh[bb][1], bh[bb][3]);
                MMA_F16(c[1][n0t], ah[ab][1][0], ah[ab][1][1], ah[ab][1][2], ah[ab][1][3],
                        bh[bb][0], bh[bb][2]);
                MMA_F16(c[1][n1t], ah[ab][1][0], ah[ab][1][1], ah[ab][1][2], ah[ab][1][3],
                        bh[bb][1], bh[bb][3]);
            }
        }
    }

    // Epilogue
#pragma unroll
    for (int mi = 0; mi < 2; mi++) {
        int r0 = m0 + warp_m * 32 + mi * 16 + (lane >> 2);
        int r1 = r0 + 8;
#pragma unroll
        for (int nt = 0; nt < 8; nt++) {
            int col = n0 + warp_n * 64 + nt * 8 + (lane & 3) * 2;
            float b0 = bias[col], b1 = bias[col + 1];
            float v00 = c[mi][nt][0] + b0, v01 = c[mi][nt][1] + b1;
            float v10 = c[mi][nt][2] + b0, v11 = c[mi][nt][3] + b1;
            if (MODE == 0) {
                *(float2*)&C[(size_t)r0 * N + col] = make_float2(v00, v01);
                *(float2*)&C[(size_t)r1 * N + col] = make_float2(v10, v11);
            } else {
                if (col < DDIM) {   // Q columns: fold 1/sqrt(hd) (exact)
                    v00 *= 0.125f; v01 *= 0.125f; v10 *= 0.125f; v11 *= 0.125f;
                }
                *(uint32_t*)&Chi[(size_t)r0 * N + col] = pack_hf2(v00, v01);
                *(uint32_t*)&Chi[(size_t)r1 * N + col] = pack_hf2(v10, v11);
            }
        }
    }
}

// ---------------------------------------------------------------------------
// HMMA flash attention, causal, fp16 (fp32 accumulate).
// 3-stage KV pipeline; Q fragments hoisted across the kt loop; fully-masked
// warps skip compute on the final diagonal tile.
// ---------------------------------------------------------------------------
#define FQARR (128 * 128)
#define FKVARR (64 * 128)
#define FKVSTAGE (2 * FKVARR)            // Kh, Vh = 16384
#define FL_SMEM (FQARR + 3 * FKVSTAGE)   // 65536 bytes

__global__ __launch_bounds__(256, 2)
void flash_hmma(const __half* __restrict__ qkv, __half* __restrict__ oh)
{
    extern __shared__ __align__(16) char smraw[];
    const uint32_t sb = smem_u32(smraw);
    const int tid = threadIdx.x, wid = tid >> 5, lane = tid & 31;
    const int qt = gridDim.x - 1 - blockIdx.x;   // LPT: big tiles first
    const int h = blockIdx.y, b = blockIdx.z;
    const size_t qrowg = (size_t)(b * SS + qt * 128);
    const int hcol = h * HDIM;
    const uint32_t lrow = lane & 15, lch = lane >> 4;

    // Q -> smem (group 0)
#pragma unroll
    for (int i = 0; i < 4; i++) {
        uint32_t idx = tid + i * 256;
        uint32_t r = idx >> 3, ch = idx & 7;
        size_t g = (qrowg + r) * QKV_LD + hcol + ch * 8;
        CP_ASYNC16(sb + sw128(r, ch), qkv + g);
    }
    CP_COMMIT();

    auto load_kv = [&](int kt, int s) {
        size_t krow = (size_t)(b * SS + kt * 64);
        uint32_t sbase = sb + FQARR + (uint32_t)s * FKVSTAGE;
#pragma unroll
        for (int i = 0; i < 2; i++) {
            uint32_t idx = tid + i * 256;
            uint32_t r = idx >> 3, ch = idx & 7;
            size_t g = (krow + r) * QKV_LD + DDIM + hcol + ch * 8;
            uint32_t so = sw128(r, ch);
            CP_ASYNC16(sbase + so,          qkv + g);          // K
            CP_ASYNC16(sbase + FKVARR + so, qkv + g + DDIM);   // V
        }
        CP_COMMIT();
    };

    const int ktmax = 2 * qt + 1;      // >= 1 always
    load_kv(0, 0);
    load_kv(1, 1);

    // Hoist Q fragments (loaded once per CTA, reused for all kt)
    CP_WAIT2();            // Q group done (kv0, kv1 may still be in flight)
    __syncthreads();
    uint32_t qf[4][4];
#pragma unroll
    for (int ks = 0; ks < 4; ks++)
        LDSM_X4(qf[ks][0], qf[ks][1], qf[ks][2], qf[ks][3],
                sb + sw128(wid * 16 + lrow, ks * 2 + lch));

    float O[8][4];
#pragma unroll
    for (int ht = 0; ht < 8; ht++)
#pragma unroll
        for (int j = 0; j < 4; j++) O[ht][j] = 0.f;
    float m0 = -CUDART_INF_F, m1 = -CUDART_INF_F, l0 = 0.f, l1 = 0.f;

    const int qr0 = qt * 128 + wid * 16 + (lane >> 2);

    for (int kt = 0; kt <= ktmax; kt++) {
        if (kt + 2 <= ktmax) CP_WAIT1(); else CP_WAIT0();
        __syncthreads();
        if (kt + 2 <= ktmax) load_kv(kt + 2, (kt + 2) % 3);
        const uint32_t kvb = sb + FQARR + (uint32_t)(kt % 3) * FKVSTAGE;

        // Last diagonal tile covers keys >= qt*128+64: warps 0-3 (rows
        // < qt*128+64) attend nothing there — skip their compute entirely.
        const bool active = !(kt == ktmax && wid < 4);
        if (active) {
            // ---- scores: S = Q·K^T ----
            float c[8][4];
#pragma unroll
            for (int nt = 0; nt < 8; nt++)
#pragma unroll
                for (int j = 0; j < 4; j++) c[nt][j] = 0.f;

#pragma unroll
            for (int ks = 0; ks < 4; ks++) {
                const uint32_t ch = ks * 2 + lch;
                uint32_t kf[4][4];
#pragma unroll
                for (int bp = 0; bp < 4; bp++)
                    LDSM_X4(kf[bp][0], kf[bp][1], kf[bp][2], kf[bp][3],
                            kvb + sw128(bp * 16 + lrow, ch));
#pragma unroll
                for (int bp = 0; bp < 4; bp++) {
                    MMA_F16(c[bp * 2],     qf[ks][0], qf[ks][1], qf[ks][2], qf[ks][3],
                            kf[bp][0], kf[bp][2]);
                    MMA_F16(c[bp * 2 + 1], qf[ks][0], qf[ks][1], qf[ks][2], qf[ks][3],
                            kf[bp][1], kf[bp][3]);
                }
            }

            // ---- causal mask (near-diagonal only) ----
            if (kt * 64 + 63 > qt * 128 + wid * 16) {
#pragma unroll
                for (int nt = 0; nt < 8; nt++) {
                    int kc = kt * 64 + nt * 8 + (lane & 3) * 2;
                    if (kc     > qr0)     c[nt][0] = -CUDART_INF_F;
                    if (kc + 1 > qr0)     c[nt][1] = -CUDART_INF_F;
                    if (kc     > qr0 + 8) c[nt][2] = -CUDART_INF_F;
                    if (kc + 1 > qr0 + 8) c[nt][3] = -CUDART_INF_F;
                }
            }

            // ---- online softmax ----
            float mt0 = -CUDART_INF_F, mt1 = -CUDART_INF_F;
#pragma unroll
            for (int nt = 0; nt < 8; nt++) {
                mt0 = fmaxf(mt0, fmaxf(c[nt][0], c[nt][1]));
                mt1 = fmaxf(mt1, fmaxf(c[nt][2], c[nt][3]));
            }
            mt0 = fmaxf(mt0, __shfl_xor_sync(0xffffffffu, mt0, 1));
            mt0 = fmaxf(mt0, __shfl_xor_sync(0xffffffffu, mt0, 2));
            mt1 = fmaxf(mt1, __shfl_xor_sync(0xffffffffu, mt1, 1));
            mt1 = fmaxf(mt1, __shfl_xor_sync(0xffffffffu, mt1, 2));

            float mn0 = fmaxf(m0, mt0), mn1 = fmaxf(m1, mt1);
            float f0 = __expf(m0 - mn0), f1 = __expf(m1 - mn1);
            float s0 = 0.f, s1 = 0.f;
            uint32_t pa0[8], pa1[8];
#pragma unroll
            for (int nt = 0; nt < 8; nt++) {
                float p0 = __expf(c[nt][0] - mn0), p1 = __expf(c[nt][1] - mn0);
                float p2 = __expf(c[nt][2] - mn1), p3 = __expf(c[nt][3] - mn1);
                s0 += p0 + p1; s1 += p2 + p3;
                pa0[nt] = pack_hf2(p0, p1);
                pa1[nt] = pack_hf2(p2, p3);
            }
            s0 += __shfl_xor_sync(0xffffffffu, s0, 1);
            s0 += __shfl_xor_sync(0xffffffffu, s0, 2);
            s1 += __shfl_xor_sync(0xffffffffu, s1, 1);
            s1 += __shfl_xor_sync(0xffffffffu, s1, 2);
            l0 = l0 * f0 + s0;  m0 = mn0;
            l1 = l1 * f1 + s1;  m1 = mn1;
#pragma unroll
            for (int ht = 0; ht < 8; ht++) {
                O[ht][0] *= f0; O[ht][1] *= f0;
                O[ht][2] *= f1; O[ht][3] *= f1;
            }

            // ---- PV: O += P·V ----
#pragma unroll
            for (int ksi = 0; ksi < 4; ksi++) {
                uint32_t a0 = pa0[2 * ksi],     a1 = pa1[2 * ksi];
                uint32_t a2 = pa0[2 * ksi + 1], a3 = pa1[2 * ksi + 1];
                uint32_t vf[4][4];
#pragma unroll
                for (int bp = 0; bp < 4; bp++)
                    LDSM_X4_T(vf[bp][0], vf[bp][1], vf[bp][2], vf[bp][3],
                              kvb + FKVARR + sw128(ksi * 16 + lrow, bp * 2 + lch));
#pragma unroll
                for (int bp = 0; bp < 2; bp++) {
                    MMA_F16(O[bp * 4 + 0], a0, a1, a2, a3, vf[bp * 2][0], vf[bp * 2][1]);
                    MMA_F16(O[bp * 4 + 1], a0, a1, a2, a3, vf[bp * 2][2], vf[bp * 2][3]);
                    MMA_F16(O[bp * 4 + 2], a0, a1, a2, a3, vf[bp * 2 + 1][0], vf[bp * 2 + 1][1]);
                    MMA_F16(O[bp * 4 + 3], a0, a1, a2, a3, vf[bp * 2 + 1][2], vf[bp * 2 + 1][3]);
                }
            }
        }
    }

    // ---- epilogue ----
    float i0 = 1.f / l0, i1 = 1.f / l1;
    size_t r0g = qrowg + wid * 16 + (lane >> 2);
    size_t r1g = r0g + 8;
    int cb = hcol + (lane & 3) * 2;
#pragma unroll
    for (int ht = 0; ht < 8; ht++) {
        int col = cb + ht * 8;
        *(uint32_t*)&oh[r0g * DDIM + col] = pack_hf2(O[ht][0] * i0, O[ht][1] * i0);
        *(uint32_t*)&oh[r1g * DDIM + col] = pack_hf2(O[ht][2] * i1, O[ht][3] * i1);
    }
}

// ---------------------------------------------------------------------------
extern "C" void kernel_launch(void* const* d_in, const int* in_sizes, int n_in,
                              void* d_out, int out_size)
{
    const float* x      = (const float*)d_in[0];
    const float* w_attn = (const float*)d_in[1];
    const float* b_attn = (const float*)d_in[2];
    const float* w_proj = (const float*)d_in[3];
    const float* b_proj = (const float*)d_in[4];
    float* out = (float*)d_out;

    __half *qkv, *xh, *w1h, *w2h, *ah;
    cudaGetSymbolAddress((void**)&qkv, g_qkv);
    cudaGetSymbolAddress((void**)&xh,  g_xh);
    cudaGetSymbolAddress((void**)&w1h, g_w1h);
    cudaGetSymbolAddress((void**)&w2h, g_w2h);
    cudaGetSymbolAddress((void**)&ah,  g_ah);

    cudaFuncSetAttribute(hmma_gemm<0>,
                         cudaFuncAttributeMaxDynamicSharedMemorySize, HMMA_SMEM);
    cudaFuncSetAttribute(hmma_gemm<1>,
                         cudaFuncAttributeMaxDynamicSharedMemorySize, HMMA_SMEM);
    cudaFuncSetAttribute(flash_hmma,
                         cudaFuncAttributeMaxDynamicSharedMemorySize, FL_SMEM);

    // Prep (single fused launch: x cast + both weight transposes)
    prep_all<<<5120, 256>>>(x, xh, w_attn, w1h, w_proj, w2h);

    // 1) QKV (fp16 out, Q pre-scaled)
    hmma_gemm<1><<<dim3(QKV_LD / 128, MM / 128), 256, HMMA_SMEM>>>(
        xh, w1h, b_attn, nullptr, qkv, DDIM, QKV_LD);

    // 2) flash attention -> fp16 attention output
    flash_hmma<<<dim3(SS / 128, HH, BB), 256, FL_SMEM>>>(qkv, ah);

    // 3) proj (fp32 out)
    hmma_gemm<0><<<dim3(DDIM / 128, MM / 128), 256, HMMA_SMEM>>>(
        ah, w2h, b_proj, out, nullptr, DDIM, DDIM);
}

// round 14
// speedup vs baseline: 1.5477x; 1.5477x over previous
#include <cuda_runtime.h>
#include <cuda_fp16.h>
#include <math_constants.h>
#include <cstdint>

#define BB 2
#define SS 2048
#define DDIM 1024
#define HH 16
#define HDIM 64
#define MM (BB*SS)          // 4096 rows
#define QKV_LD 3072         // 3*D

// ---------------------------------------------------------------------------
// Scratch (device globals: allowed; runtime allocs are not)
// ---------------------------------------------------------------------------
__device__ __half g_qkv[(size_t)MM * QKV_LD];    // QKV fp16 (Q pre-scaled)
__device__ __half g_xh[(size_t)MM * DDIM];       // x fp16
__device__ __half g_w1h[(size_t)QKV_LD * DDIM];  // w_attn^T fp16 [3072,1024]
__device__ __half g_w2h[(size_t)DDIM * DDIM];    // w_proj^T fp16 [1024,1024]
__device__ __half g_ah[(size_t)MM * DDIM];       // attention out fp16

// ---------------------------------------------------------------------------
// Portable PTX helpers
// ---------------------------------------------------------------------------
__device__ __forceinline__ uint32_t smem_u32(const void* p) {
    uint32_t a;
    asm("{ .reg .u64 t; cvta.to.shared.u64 t, %1; cvt.u32.u64 %0, t; }"
        : "=r"(a) : "l"(p));
    return a;
}

#define CP_ASYNC16(sa, gp) \
    asm volatile("cp.async.cg.shared.global [%0], [%1], 16;" :: "r"(sa), "l"(gp))
#define CP_COMMIT() asm volatile("cp.async.commit_group;" ::: "memory")
#define CP_WAIT1()  asm volatile("cp.async.wait_group 1;" ::: "memory")
#define CP_WAIT0()  asm volatile("cp.async.wait_group 0;" ::: "memory")

#define LDSM_X4(r0, r1, r2, r3, addr) \
    asm volatile("ldmatrix.sync.aligned.m8n8.x4.shared.b16 {%0,%1,%2,%3}, [%4];" \
        : "=r"(r0), "=r"(r1), "=r"(r2), "=r"(r3) : "r"(addr))

#define LDSM_X4_T(r0, r1, r2, r3, addr) \
    asm volatile("ldmatrix.sync.aligned.m8n8.x4.trans.shared.b16 {%0,%1,%2,%3}, [%4];" \
        : "=r"(r0), "=r"(r1), "=r"(r2), "=r"(r3) : "r"(addr))

#define MMA_F16(c, a0, a1, a2, a3, b0, b1) \
    asm volatile("mma.sync.aligned.m16n8k16.row.col.f32.f16.f16.f32 " \
        "{%0,%1,%2,%3}, {%4,%5,%6,%7}, {%8,%9}, {%0,%1,%2,%3};" \
        : "+f"((c)[0]), "+f"((c)[1]), "+f"((c)[2]), "+f"((c)[3]) \
        : "r"(a0), "r"(a1), "r"(a2), "r"(a3), "r"(b0), "r"(b1))

__device__ __forceinline__ uint32_t pack_hf2(float a, float b) {
    __half2 t = __floats2half2_rn(a, b);
    return *(uint32_t*)&t;
}

// XOR swizzle for 128B rows (ch in 0..7): conflict-free per 8-lane phase.
__device__ __forceinline__ uint32_t sw128(uint32_t r, uint32_t ch) {
    return r * 128 + ((ch ^ (r & 7)) << 4);
}

// ---------------------------------------------------------------------------
// Fused prep: one launch does x->fp16 cast + both weight transposes.
// ---------------------------------------------------------------------------
__device__ __forceinline__ void transpose_body(const float* __restrict__ W,
                                               __half* __restrict__ hi,
                                               int K, int N, int bx, int by,
                                               int tid)
{
    __shared__ float t[32][33];
    int n0 = bx * 32, k0 = by * 32;
    int tx = tid & 31, ty = tid >> 5;
#pragma unroll
    for (int i = 0; i < 32; i += 8)
        t[ty + i][tx] = W[(size_t)(k0 + ty + i) * N + n0 + tx];
    __syncthreads();
#pragma unroll
    for (int i = 0; i < 32; i += 8)
        hi[(size_t)(n0 + ty + i) * K + k0 + tx] = __float2half(t[tx][ty + i]);
}

__global__ void prep_all(const float* __restrict__ x, __half* __restrict__ xh,
                         const float* __restrict__ w1, __half* __restrict__ w1h,
                         const float* __restrict__ w2, __half* __restrict__ w2h)
{
    const int bid = blockIdx.x, tid = threadIdx.x;
    if (bid < 1024) {
        const int n4 = MM * DDIM / 4;
        for (int i = bid * 256 + tid; i < n4; i += 1024 * 256) {
            float4 v = ((const float4*)x)[i];
            ((uint32_t*)xh)[2 * i]     = pack_hf2(v.x, v.y);
            ((uint32_t*)xh)[2 * i + 1] = pack_hf2(v.z, v.w);
        }
    } else if (bid < 4096) {
        int t = bid - 1024;                       // 96 x 32 blocks
        transpose_body(w1, w1h, DDIM, QKV_LD, t % 96, t / 96, tid);
    } else {
        int t = bid - 4096;                       // 32 x 32 blocks
        transpose_body(w2, w2h, DDIM, DDIM, t % 32, t / 32, tid);
    }
}

// ---------------------------------------------------------------------------
// HMMA fp16 GEMM + bias (fp32 accumulate): C = Ah @ Bh^T + bias
// R12 version (best measured): 128x128 CTA, 32x64 warp tile, K-tile 64,
// 3-stage cp.async, register double-buffered fragments.
// MODE 0: fp32 C.  MODE 1: fp16 C (Q cols scaled 0.125).
// ---------------------------------------------------------------------------
#define GARR 16384
#define GSTAGE (2 * GARR)            // 32768
#define HMMA_SMEM (3 * GSTAGE)       // 98304 -> 2 CTAs/SM

template<int MODE>
__global__ __launch_bounds__(256, 2)
void hmma_gemm(const __half* __restrict__ Ah, const __half* __restrict__ Bh,
               const float* __restrict__ bias, float* __restrict__ C,
               __half* __restrict__ Chi, int K, int N)
{
    extern __shared__ __align__(16) char smraw[];
    const uint32_t sb = smem_u32(smraw);

    const int tid = threadIdx.x;
    const int wid = tid >> 5, lane = tid & 31;
    const int m0 = blockIdx.y * 128, n0 = blockIdx.x * 128;
    const int warp_m = wid & 3;
    const int warp_n = wid >> 2;

    float c[2][8][4];
#pragma unroll
    for (int mi = 0; mi < 2; mi++)
#pragma unroll
        for (int nt = 0; nt < 8; nt++)
#pragma unroll
            for (int j = 0; j < 4; j++) c[mi][nt][j] = 0.f;

    const int nkt = K / 64;

    auto load_stage = [&](int kt, int slot) {
        const int k0 = kt * 64;
        const uint32_t sbase = sb + (uint32_t)slot * GSTAGE;
#pragma unroll
        for (int arr = 0; arr < 2; arr++) {
            const __half* P = (arr == 0) ? Ah : Bh;
            const int rowbase = (arr == 0) ? m0 : n0;
#pragma unroll
            for (int i = 0; i < 4; i++) {
                uint32_t idx = tid + i * 256;
                uint32_t r = idx >> 3, ch = idx & 7;
                const __half* gp = P + (size_t)(rowbase + r) * K + k0 + ch * 8;
                CP_ASYNC16(sbase + arr * GARR + sw128(r, ch), gp);
            }
        }
        CP_COMMIT();
    };

    load_stage(0, 0);
    load_stage(1, 1);

    const uint32_t lrow = lane & 15;
    const uint32_t lch  = lane >> 4;
    const uint32_t aRow = (uint32_t)(warp_m * 32) + lrow;
    const uint32_t bRow = (uint32_t)(warp_n * 64) + lrow;

    for (int kt = 0; kt < nkt; kt++) {
        if (kt + 2 < nkt) CP_WAIT1(); else CP_WAIT0();
        __syncthreads();
        if (kt + 2 < nkt) load_stage(kt + 2, (kt + 2) % 3);

        const uint32_t sbase = sb + (uint32_t)(kt % 3) * GSTAGE;

        uint32_t ah[2][2][4];   // [buf][mi][frag]
        uint32_t bh[2][4];      // [buf][frag]

        {
            const uint32_t ch = lch;
            LDSM_X4(ah[0][0][0], ah[0][0][1], ah[0][0][2], ah[0][0][3],
                    sbase + sw128(aRow, ch));
            LDSM_X4(ah[0][1][0], ah[0][1][1], ah[0][1][2], ah[0][1][3],
                    sbase + sw128(aRow + 16, ch));
            LDSM_X4(bh[0][0], bh[0][1], bh[0][2], bh[0][3],
                    sbase + GARR + sw128(bRow, ch));
        }

#pragma unroll
        for (int ks = 0; ks < 4; ks++) {
            const int ab = ks & 1;
#pragma unroll
            for (int np = 0; np < 4; np++) {
                const int bb = np & 1;
                if (np < 3) {
                    const uint32_t ch = ks * 2 + lch;
                    LDSM_X4(bh[bb ^ 1][0], bh[bb ^ 1][1], bh[bb ^ 1][2], bh[bb ^ 1][3],
                            sbase + GARR + sw128(bRow + (np + 1) * 16, ch));
                } else if (ks < 3) {
                    const uint32_t ch = (ks + 1) * 2 + lch;
                    LDSM_X4(ah[ab ^ 1][0][0], ah[ab ^ 1][0][1], ah[ab ^ 1][0][2], ah[ab ^ 1][0][3],
                            sbase + sw128(aRow, ch));
                    LDSM_X4(ah[ab ^ 1][1][0], ah[ab ^ 1][1][1], ah[ab ^ 1][1][2], ah[ab ^ 1][1][3],
                            sbase + sw128(aRow + 16, ch));
                    LDSM_X4(bh[bb ^ 1][0], bh[bb ^ 1][1], bh[bb ^ 1][2], bh[bb ^ 1][3],
                            sbase + GARR + sw128(bRow, ch));
                }
                const int n0t = np * 2, n1t = np * 2 + 1;
                MMA_F16(c[0][n0t], ah[ab][0][0], ah[ab][0][1], ah[ab][0][2], ah[ab][0][3],
                        bh[bb][0], bh[bb][2]);
                MMA_F16(c[0][n1t], ah[ab][0][0], ah[ab][0][1], ah[ab][0][2], ah[ab][0][3],
                        bh[bb][1], bh[bb][3]);
                MMA_F16(c[1][n0t], ah[ab][1][0], ah[ab][1][1], ah[ab][1][2], ah[ab][1][3],
                        bh[bb][0], bh[bb][2]);
                MMA_F16(c[1][n1t], ah[ab][1][0], ah[ab][1][1], ah[ab][1][2], ah[ab][1][3],
                        bh[bb][1], bh[bb][3]);
            }
        }
    }

    // Epilogue
#pragma unroll
    for (int mi = 0; mi < 2; mi++) {
        int r0 = m0 + warp_m * 32 + mi * 16 + (lane >> 2);
        int r1 = r0 + 8;
#pragma unroll
        for (int nt = 0; nt < 8; nt++) {
            int col = n0 + warp_n * 64 + nt * 8 + (lane & 3) * 2;
            float b0 = bias[col], b1 = bias[col + 1];
            float v00 = c[mi][nt][0] + b0, v01 = c[mi][nt][1] + b1;
            float v10 = c[mi][nt][2] + b0, v11 = c[mi][nt][3] + b1;
            if (MODE == 0) {
                *(float2*)&C[(size_t)r0 * N + col] = make_float2(v00, v01);
                *(float2*)&C[(size_t)r1 * N + col] = make_float2(v10, v11);
            } else {
                if (col < DDIM) {   // Q columns: fold 1/sqrt(hd) (exact)
                    v00 *= 0.125f; v01 *= 0.125f; v10 *= 0.125f; v11 *= 0.125f;
                }
                *(uint32_t*)&Chi[(size_t)r0 * N + col] = pack_hf2(v00, v01);
                *(uint32_t*)&Chi[(size_t)r1 * N + col] = pack_hf2(v10, v11);
            }
        }
    }
}

// ---------------------------------------------------------------------------
// HMMA flash attention, causal, fp16 (fp32 accumulate).
// R12 structure (per-ks Q LDSM — NO persistent Q hoist), 3-stage KV pipeline,
// + masked-warp skip on the final diagonal tile only.
// ---------------------------------------------------------------------------
#define FQARR (128 * 128)
#define FKVARR (64 * 128)
#define FKVSTAGE (2 * FKVARR)            // Kh, Vh = 16384
#define FL_SMEM (FQARR + 3 * FKVSTAGE)   // 65536 bytes

__global__ __launch_bounds__(256, 2)
void flash_hmma(const __half* __restrict__ qkv, __half* __restrict__ oh)
{
    extern __shared__ __align__(16) char smraw[];
    const uint32_t sb = smem_u32(smraw);
    const int tid = threadIdx.x, wid = tid >> 5, lane = tid & 31;
    const int qt = gridDim.x - 1 - blockIdx.x;
    const int h = blockIdx.y, b = blockIdx.z;
    const size_t qrowg = (size_t)(b * SS + qt * 128);
    const int hcol = h * HDIM;
    const uint32_t lrow = lane & 15, lch = lane >> 4;

    // Q -> smem (group 0)
#pragma unroll
    for (int i = 0; i < 4; i++) {
        uint32_t idx = tid + i * 256;
        uint32_t r = idx >> 3, ch = idx & 7;
        size_t g = (qrowg + r) * QKV_LD + hcol + ch * 8;
        CP_ASYNC16(sb + sw128(r, ch), qkv + g);
    }
    CP_COMMIT();

    auto load_kv = [&](int kt, int s) {
        size_t krow = (size_t)(b * SS + kt * 64);
        uint32_t sbase = sb + FQARR + (uint32_t)s * FKVSTAGE;
#pragma unroll
        for (int i = 0; i < 2; i++) {
            uint32_t idx = tid + i * 256;
            uint32_t r = idx >> 3, ch = idx & 7;
            size_t g = (krow + r) * QKV_LD + DDIM + hcol + ch * 8;
            uint32_t so = sw128(r, ch);
            CP_ASYNC16(sbase + so,          qkv + g);          // K
            CP_ASYNC16(sbase + FKVARR + so, qkv + g + DDIM);   // V
        }
        CP_COMMIT();
    };

    const int ktmax = 2 * qt + 1;      // >= 1 always
    load_kv(0, 0);
    load_kv(1, 1);

    float O[8][4];
#pragma unroll
    for (int ht = 0; ht < 8; ht++)
#pragma unroll
        for (int j = 0; j < 4; j++) O[ht][j] = 0.f;
    float m0 = -CUDART_INF_F, m1 = -CUDART_INF_F, l0 = 0.f, l1 = 0.f;

    const int qr0 = qt * 128 + wid * 16 + (lane >> 2);

    for (int kt = 0; kt <= ktmax; kt++) {
        if (kt + 2 <= ktmax) CP_WAIT1(); else CP_WAIT0();
        __syncthreads();
        if (kt + 2 <= ktmax) load_kv(kt + 2, (kt + 2) % 3);
        const uint32_t kvb = sb + FQARR + (uint32_t)(kt % 3) * FKVSTAGE;

        // Last diagonal tile covers keys >= qt*128+64: warps 0-3 attend
        // nothing there — skip their compute (barriers already done above).
        if (kt == ktmax && wid < 4) continue;

        // ---- scores: S = Q·K^T (all 5 LDSM hoisted before 16 MMAs) ----
        float c[8][4];
#pragma unroll
        for (int nt = 0; nt < 8; nt++)
#pragma unroll
            for (int j = 0; j < 4; j++) c[nt][j] = 0.f;

#pragma unroll
        for (int ks = 0; ks < 4; ks++) {
            const uint32_t ch = ks * 2 + lch;
            uint32_t q0, q1, q2, q3;
            uint32_t kf[4][4];
            LDSM_X4(q0, q1, q2, q3, sb + sw128(wid * 16 + lrow, ch));
#pragma unroll
            for (int bp = 0; bp < 4; bp++)
                LDSM_X4(kf[bp][0], kf[bp][1], kf[bp][2], kf[bp][3],
                        kvb + sw128(bp * 16 + lrow, ch));
#pragma unroll
            for (int bp = 0; bp < 4; bp++) {
                MMA_F16(c[bp * 2],     q0, q1, q2, q3, kf[bp][0], kf[bp][2]);
                MMA_F16(c[bp * 2 + 1], q0, q1, q2, q3, kf[bp][1], kf[bp][3]);
            }
        }

        // ---- causal mask ----
        if (kt * 64 + 63 > qt * 128 + wid * 16) {
#pragma unroll
            for (int nt = 0; nt < 8; nt++) {
                int kc = kt * 64 + nt * 8 + (lane & 3) * 2;
                if (kc     > qr0)     c[nt][0] = -CUDART_INF_F;
                if (kc + 1 > qr0)     c[nt][1] = -CUDART_INF_F;
                if (kc     > qr0 + 8) c[nt][2] = -CUDART_INF_F;
                if (kc + 1 > qr0 + 8) c[nt][3] = -CUDART_INF_F;
            }
        }

        // ---- online softmax ----
        float mt0 = -CUDART_INF_F, mt1 = -CUDART_INF_F;
#pragma unroll
        for (int nt = 0; nt < 8; nt++) {
            mt0 = fmaxf(mt0, fmaxf(c[nt][0], c[nt][1]));
            mt1 = fmaxf(mt1, fmaxf(c[nt][2], c[nt][3]));
        }
        mt0 = fmaxf(mt0, __shfl_xor_sync(0xffffffffu, mt0, 1));
        mt0 = fmaxf(mt0, __shfl_xor_sync(0xffffffffu, mt0, 2));
        mt1 = fmaxf(mt1, __shfl_xor_sync(0xffffffffu, mt1, 1));
        mt1 = fmaxf(mt1, __shfl_xor_sync(0xffffffffu, mt1, 2));

        float mn0 = fmaxf(m0, mt0), mn1 = fmaxf(m1, mt1);
        float f0 = __expf(m0 - mn0), f1 = __expf(m1 - mn1);
        float s0 = 0.f, s1 = 0.f;
        uint32_t pa0[8], pa1[8];
#pragma unroll
        for (int nt = 0; nt < 8; nt++) {
            float p0 = __expf(c[nt][0] - mn0), p1 = __expf(c[nt][1] - mn0);
            float p2 = __expf(c[nt][2] - mn1), p3 = __expf(c[nt][3] - mn1);
            s0 += p0 + p1; s1 += p2 + p3;
            pa0[nt] = pack_hf2(p0, p1);
            pa1[nt] = pack_hf2(p2, p3);
        }
        s0 += __shfl_xor_sync(0xffffffffu, s0, 1);
        s0 += __shfl_xor_sync(0xffffffffu, s0, 2);
        s1 += __shfl_xor_sync(0xffffffffu, s1, 1);
        s1 += __shfl_xor_sync(0xffffffffu, s1, 2);
        l0 = l0 * f0 + s0;  m0 = mn0;
        l1 = l1 * f1 + s1;  m1 = mn1;
#pragma unroll
        for (int ht = 0; ht < 8; ht++) {
            O[ht][0] *= f0; O[ht][1] *= f0;
            O[ht][2] *= f1; O[ht][3] *= f1;
        }

        // ---- PV: O += P·V (all 4 LDSM hoisted before 16 MMAs) ----
#pragma unroll
        for (int ksi = 0; ksi < 4; ksi++) {
            uint32_t a0 = pa0[2 * ksi],     a1 = pa1[2 * ksi];
            uint32_t a2 = pa0[2 * ksi + 1], a3 = pa1[2 * ksi + 1];
            uint32_t vf[4][4];
#pragma unroll
            for (int bp = 0; bp < 4; bp++)
                LDSM_X4_T(vf[bp][0], vf[bp][1], vf[bp][2], vf[bp][3],
                          kvb + FKVARR + sw128(ksi * 16 + lrow, bp * 2 + lch));
#pragma unroll
            for (int bp = 0; bp < 2; bp++) {
                MMA_F16(O[bp * 4 + 0], a0, a1, a2, a3, vf[bp * 2][0], vf[bp * 2][1]);
                MMA_F16(O[bp * 4 + 1], a0, a1, a2, a3, vf[bp * 2][2], vf[bp * 2][3]);
                MMA_F16(O[bp * 4 + 2], a0, a1, a2, a3, vf[bp * 2 + 1][0], vf[bp * 2 + 1][1]);
                MMA_F16(O[bp * 4 + 3], a0, a1, a2, a3, vf[bp * 2 + 1][2], vf[bp * 2 + 1][3]);
            }
        }
    }

    // ---- epilogue ----
    float i0 = 1.f / l0, i1 = 1.f / l1;
    size_t r0g = qrowg + wid * 16 + (lane >> 2);
    size_t r1g = r0g + 8;
    int cb = hcol + (lane & 3) * 2;
#pragma unroll
    for (int ht = 0; ht < 8; ht++) {
        int col = cb + ht * 8;
        *(uint32_t*)&oh[r0g * DDIM + col] = pack_hf2(O[ht][0] * i0, O[ht][1] * i0);
        *(uint32_t*)&oh[r1g * DDIM + col] = pack_hf2(O[ht][2] * i1, O[ht][3] * i1);
    }
}

// ---------------------------------------------------------------------------
extern "C" void kernel_launch(void* const* d_in, const int* in_sizes, int n_in,
                              void* d_out, int out_size)
{
    const float* x      = (const float*)d_in[0];
    const float* w_attn = (const float*)d_in[1];
    const float* b_attn = (const float*)d_in[2];
    const float* w_proj = (const float*)d_in[3];
    const float* b_proj = (const float*)d_in[4];
    float* out = (float*)d_out;

    __half *qkv, *xh, *w1h, *w2h, *ah;
    cudaGetSymbolAddress((void**)&qkv, g_qkv);
    cudaGetSymbolAddress((void**)&xh,  g_xh);
    cudaGetSymbolAddress((void**)&w1h, g_w1h);
    cudaGetSymbolAddress((void**)&w2h, g_w2h);
    cudaGetSymbolAddress((void**)&ah,  g_ah);

    cudaFuncSetAttribute(hmma_gemm<0>,
                         cudaFuncAttributeMaxDynamicSharedMemorySize, HMMA_SMEM);
    cudaFuncSetAttribute(hmma_gemm<1>,
                         cudaFuncAttributeMaxDynamicSharedMemorySize, HMMA_SMEM);
    cudaFuncSetAttribute(flash_hmma,
                         cudaFuncAttributeMaxDynamicSharedMemorySize, FL_SMEM);

    // Prep (single fused launch: x cast + both weight transposes)
    prep_all<<<5120, 256>>>(x, xh, w_attn, w1h, w_proj, w2h);

    // 1) QKV (fp16 out, Q pre-scaled)
    hmma_gemm<1><<<dim3(QKV_LD / 128, MM / 128), 256, HMMA_SMEM>>>(
        xh, w1h, b_attn, nullptr, qkv, DDIM, QKV_LD);

    // 2) flash attention -> fp16 attention output
    flash_hmma<<<dim3(SS / 128, HH, BB), 256, FL_SMEM>>>(qkv, ah);

    // 3) proj (fp32 out)
    hmma_gemm<0><<<dim3(DDIM / 128, MM / 128), 256, HMMA_SMEM>>>(
        ah, w2h, b_proj, out, nullptr, DDIM, DDIM);
}

// round 15
// speedup vs baseline: 1.6862x; 1.0895x over previous
#include <cuda_runtime.h>
#include <cuda_fp16.h>
#include <math_constants.h>
#include <cstdint>

#define BB 2
#define SS 2048
#define DDIM 1024
#define HH 16
#define HDIM 64
#define MM (BB*SS)          // 4096 rows
#define QKV_LD 3072         // 3*D
#define NQT (SS/128)        // 16 q-tiles

// ---------------------------------------------------------------------------
// Scratch (device globals: allowed; runtime allocs are not)
// ---------------------------------------------------------------------------
__device__ __half g_qkv[(size_t)MM * QKV_LD];    // QKV fp16 (Q pre-scaled)
__device__ __half g_xh[(size_t)MM * DDIM];       // x fp16
__device__ __half g_w1h[(size_t)QKV_LD * DDIM];  // w_attn^T fp16 [3072,1024]
__device__ __half g_w2h[(size_t)DDIM * DDIM];    // w_proj^T fp16 [1024,1024]
__device__ __half g_ah[(size_t)MM * DDIM];       // attention out fp16

// ---------------------------------------------------------------------------
// Portable PTX helpers
// ---------------------------------------------------------------------------
__device__ __forceinline__ uint32_t smem_u32(const void* p) {
    uint32_t a;
    asm("{ .reg .u64 t; cvta.to.shared.u64 t, %1; cvt.u32.u64 %0, t; }"
        : "=r"(a) : "l"(p));
    return a;
}

#define CP_ASYNC16(sa, gp) \
    asm volatile("cp.async.cg.shared.global [%0], [%1], 16;" :: "r"(sa), "l"(gp))
#define CP_COMMIT() asm volatile("cp.async.commit_group;" ::: "memory")
#define CP_WAIT1()  asm volatile("cp.async.wait_group 1;" ::: "memory")
#define CP_WAIT0()  asm volatile("cp.async.wait_group 0;" ::: "memory")

#define LDSM_X4(r0, r1, r2, r3, addr) \
    asm volatile("ldmatrix.sync.aligned.m8n8.x4.shared.b16 {%0,%1,%2,%3}, [%4];" \
        : "=r"(r0), "=r"(r1), "=r"(r2), "=r"(r3) : "r"(addr))

#define LDSM_X4_T(r0, r1, r2, r3, addr) \
    asm volatile("ldmatrix.sync.aligned.m8n8.x4.trans.shared.b16 {%0,%1,%2,%3}, [%4];" \
        : "=r"(r0), "=r"(r1), "=r"(r2), "=r"(r3) : "r"(addr))

#define MMA_F16(c, a0, a1, a2, a3, b0, b1) \
    asm volatile("mma.sync.aligned.m16n8k16.row.col.f32.f16.f16.f32 " \
        "{%0,%1,%2,%3}, {%4,%5,%6,%7}, {%8,%9}, {%0,%1,%2,%3};" \
        : "+f"((c)[0]), "+f"((c)[1]), "+f"((c)[2]), "+f"((c)[3]) \
        : "r"(a0), "r"(a1), "r"(a2), "r"(a3), "r"(b0), "r"(b1))

__device__ __forceinline__ uint32_t pack_hf2(float a, float b) {
    __half2 t = __floats2half2_rn(a, b);
    return *(uint32_t*)&t;
}

// XOR swizzle for 128B rows (ch in 0..7): conflict-free per 8-lane phase.
__device__ __forceinline__ uint32_t sw128(uint32_t r, uint32_t ch) {
    return r * 128 + ((ch ^ (r & 7)) << 4);
}

// ---------------------------------------------------------------------------
// Fused prep: one launch does x->fp16 cast + both weight transposes.
// ---------------------------------------------------------------------------
__device__ __forceinline__ void transpose_body(const float* __restrict__ W,
                                               __half* __restrict__ hi,
                                               int K, int N, int bx, int by,
                                               int tid)
{
    __shared__ float t[32][33];
    int n0 = bx * 32, k0 = by * 32;
    int tx = tid & 31, ty = tid >> 5;
#pragma unroll
    for (int i = 0; i < 32; i += 8)
        t[ty + i][tx] = W[(size_t)(k0 + ty + i) * N + n0 + tx];
    __syncthreads();
#pragma unroll
    for (int i = 0; i < 32; i += 8)
        hi[(size_t)(n0 + ty + i) * K + k0 + tx] = __float2half(t[tx][ty + i]);
}

__global__ void prep_all(const float* __restrict__ x, __half* __restrict__ xh,
                         const float* __restrict__ w1, __half* __restrict__ w1h,
                         const float* __restrict__ w2, __half* __restrict__ w2h)
{
    const int bid = blockIdx.x, tid = threadIdx.x;
    if (bid < 1024) {
        const int n4 = MM * DDIM / 4;
        for (int i = bid * 256 + tid; i < n4; i += 1024 * 256) {
            float4 v = ((const float4*)x)[i];
            ((uint32_t*)xh)[2 * i]     = pack_hf2(v.x, v.y);
            ((uint32_t*)xh)[2 * i + 1] = pack_hf2(v.z, v.w);
        }
    } else if (bid < 4096) {
        int t = bid - 1024;                       // 96 x 32 blocks
        transpose_body(w1, w1h, DDIM, QKV_LD, t % 96, t / 96, tid);
    } else {
        int t = bid - 4096;                       // 32 x 32 blocks
        transpose_body(w2, w2h, DDIM, DDIM, t % 32, t / 32, tid);
    }
}

// ---------------------------------------------------------------------------
// HMMA fp16 GEMM + bias (fp32 accumulate): C = Ah @ Bh^T + bias
// R12/R14 version (best measured): 128x128 CTA, 32x64 warp tile, K-tile 64,
// 3-stage cp.async, register double-buffered fragments.
// MODE 0: fp32 C.  MODE 1: fp16 C (Q cols scaled 0.125).
// ---------------------------------------------------------------------------
#define GARR 16384
#define GSTAGE (2 * GARR)            // 32768
#define HMMA_SMEM (3 * GSTAGE)       // 98304 -> 2 CTAs/SM

template<int MODE>
__global__ __launch_bounds__(256, 2)
void hmma_gemm(const __half* __restrict__ Ah, const __half* __restrict__ Bh,
               const float* __restrict__ bias, float* __restrict__ C,
               __half* __restrict__ Chi, int K, int N)
{
    extern __shared__ __align__(16) char smraw[];
    const uint32_t sb = smem_u32(smraw);

    const int tid = threadIdx.x;
    const int wid = tid >> 5, lane = tid & 31;
    const int m0 = blockIdx.y * 128, n0 = blockIdx.x * 128;
    const int warp_m = wid & 3;
    const int warp_n = wid >> 2;

    float c[2][8][4];
#pragma unroll
    for (int mi = 0; mi < 2; mi++)
#pragma unroll
        for (int nt = 0; nt < 8; nt++)
#pragma unroll
            for (int j = 0; j < 4; j++) c[mi][nt][j] = 0.f;

    const int nkt = K / 64;

    auto load_stage = [&](int kt, int slot) {
        const int k0 = kt * 64;
        const uint32_t sbase = sb + (uint32_t)slot * GSTAGE;
#pragma unroll
        for (int arr = 0; arr < 2; arr++) {
            const __half* P = (arr == 0) ? Ah : Bh;
            const int rowbase = (arr == 0) ? m0 : n0;
#pragma unroll
            for (int i = 0; i < 4; i++) {
                uint32_t idx = tid + i * 256;
                uint32_t r = idx >> 3, ch = idx & 7;
                const __half* gp = P + (size_t)(rowbase + r) * K + k0 + ch * 8;
                CP_ASYNC16(sbase + arr * GARR + sw128(r, ch), gp);
            }
        }
        CP_COMMIT();
    };

    load_stage(0, 0);
    load_stage(1, 1);

    const uint32_t lrow = lane & 15;
    const uint32_t lch  = lane >> 4;
    const uint32_t aRow = (uint32_t)(warp_m * 32) + lrow;
    const uint32_t bRow = (uint32_t)(warp_n * 64) + lrow;

    for (int kt = 0; kt < nkt; kt++) {
        if (kt + 2 < nkt) CP_WAIT1(); else CP_WAIT0();
        __syncthreads();
        if (kt + 2 < nkt) load_stage(kt + 2, (kt + 2) % 3);

        const uint32_t sbase = sb + (uint32_t)(kt % 3) * GSTAGE;

        uint32_t ah[2][2][4];   // [buf][mi][frag]
        uint32_t bh[2][4];      // [buf][frag]

        {
            const uint32_t ch = lch;
            LDSM_X4(ah[0][0][0], ah[0][0][1], ah[0][0][2], ah[0][0][3],
                    sbase + sw128(aRow, ch));
            LDSM_X4(ah[0][1][0], ah[0][1][1], ah[0][1][2], ah[0][1][3],
                    sbase + sw128(aRow + 16, ch));
            LDSM_X4(bh[0][0], bh[0][1], bh[0][2], bh[0][3],
                    sbase + GARR + sw128(bRow, ch));
        }

#pragma unroll
        for (int ks = 0; ks < 4; ks++) {
            const int ab = ks & 1;
#pragma unroll
            for (int np = 0; np < 4; np++) {
                const int bb = np & 1;
                if (np < 3) {
                    const uint32_t ch = ks * 2 + lch;
                    LDSM_X4(bh[bb ^ 1][0], bh[bb ^ 1][1], bh[bb ^ 1][2], bh[bb ^ 1][3],
                            sbase + GARR + sw128(bRow + (np + 1) * 16, ch));
                } else if (ks < 3) {
                    const uint32_t ch = (ks + 1) * 2 + lch;
                    LDSM_X4(ah[ab ^ 1][0][0], ah[ab ^ 1][0][1], ah[ab ^ 1][0][2], ah[ab ^ 1][0][3],
                            sbase + sw128(aRow, ch));
                    LDSM_X4(ah[ab ^ 1][1][0], ah[ab ^ 1][1][1], ah[ab ^ 1][1][2], ah[ab ^ 1][1][3],
                            sbase + sw128(aRow + 16, ch));
                    LDSM_X4(bh[bb ^ 1][0], bh[bb ^ 1][1], bh[bb ^ 1][2], bh[bb ^ 1][3],
                            sbase + GARR + sw128(bRow, ch));
                }
                const int n0t = np * 2, n1t = np * 2 + 1;
                MMA_F16(c[0][n0t], ah[ab][0][0], ah[ab][0][1], ah[ab][0][2], ah[ab][0][3],
                        bh[bb][0], bh[bb][2]);
                MMA_F16(c[0][n1t], ah[ab][0][0], ah[ab][0][1], ah[ab][0][2], ah[ab][0][3],
                        bh[bb][1], bh[bb][3]);
                MMA_F16(c[1][n0t], ah[ab][1][0], ah[ab][1][1], ah[ab][1][2], ah[ab][1][3],
                        bh[bb][0], bh[bb][2]);
                MMA_F16(c[1][n1t], ah[ab][1][0], ah[ab][1][1], ah[ab][1][2], ah[ab][1][3],
                        bh[bb][1], bh[bb][3]);
            }
        }
    }

    // Epilogue
#pragma unroll
    for (int mi = 0; mi < 2; mi++) {
        int r0 = m0 + warp_m * 32 + mi * 16 + (lane >> 2);
        int r1 = r0 + 8;
#pragma unroll
        for (int nt = 0; nt < 8; nt++) {
            int col = n0 + warp_n * 64 + nt * 8 + (lane & 3) * 2;
            float b0 = bias[col], b1 = bias[col + 1];
            float v00 = c[mi][nt][0] + b0, v01 = c[mi][nt][1] + b1;
            float v10 = c[mi][nt][2] + b0, v11 = c[mi][nt][3] + b1;
            if (MODE == 0) {
                *(float2*)&C[(size_t)r0 * N + col] = make_float2(v00, v01);
                *(float2*)&C[(size_t)r1 * N + col] = make_float2(v10, v11);
            } else {
                if (col < DDIM) {   // Q columns: fold 1/sqrt(hd) (exact)
                    v00 *= 0.125f; v01 *= 0.125f; v10 *= 0.125f; v11 *= 0.125f;
                }
                *(uint32_t*)&Chi[(size_t)r0 * N + col] = pack_hf2(v00, v01);
                *(uint32_t*)&Chi[(size_t)r1 * N + col] = pack_hf2(v10, v11);
            }
        }
    }
}

// ---------------------------------------------------------------------------
// HMMA flash attention, causal, fp16 (fp32 accumulate).
// 1-D LPT grid (qt strictly descending), 3-stage KV pipeline, masked-warp
// skip on final tile + warp-uniform skip of fully-masked 16-key sub-tiles.
// ---------------------------------------------------------------------------
#define FQARR (128 * 128)
#define FKVARR (64 * 128)
#define FKVSTAGE (2 * FKVARR)            // Kh, Vh = 16384
#define FL_SMEM (FQARR + 3 * FKVSTAGE)   // 65536 bytes

__global__ __launch_bounds__(256, 2)
void flash_hmma(const __half* __restrict__ qkv, __half* __restrict__ oh)
{
    extern __shared__ __align__(16) char smraw[];
    const uint32_t sb = smem_u32(smraw);
    const int tid = threadIdx.x, wid = tid >> 5, lane = tid & 31;
    // LPT: blockIdx.x enumerates (qt descending) x (h,b); wave 1 gets the
    // longest tiles so the tail is all short tiles.
    const int bid = blockIdx.x;
    const int qt = (NQT - 1) - (bid >> 5);    // 32 = HH*BB tiles per qt
    const int hb = bid & 31;
    const int h = hb >> 1, b = hb & 1;
    const size_t qrowg = (size_t)(b * SS + qt * 128);
    const int hcol = h * HDIM;
    const uint32_t lrow = lane & 15, lch = lane >> 4;

    // Q -> smem (group 0)
#pragma unroll
    for (int i = 0; i < 4; i++) {
        uint32_t idx = tid + i * 256;
        uint32_t r = idx >> 3, ch = idx & 7;
        size_t g = (qrowg + r) * QKV_LD + hcol + ch * 8;
        CP_ASYNC16(sb + sw128(r, ch), qkv + g);
    }
    CP_COMMIT();

    auto load_kv = [&](int kt, int s) {
        size_t krow = (size_t)(b * SS + kt * 64);
        uint32_t sbase = sb + FQARR + (uint32_t)s * FKVSTAGE;
#pragma unroll
        for (int i = 0; i < 2; i++) {
            uint32_t idx = tid + i * 256;
            uint32_t r = idx >> 3, ch = idx & 7;
            size_t g = (krow + r) * QKV_LD + DDIM + hcol + ch * 8;
            uint32_t so = sw128(r, ch);
            CP_ASYNC16(sbase + so,          qkv + g);          // K
            CP_ASYNC16(sbase + FKVARR + so, qkv + g + DDIM);   // V
        }
        CP_COMMIT();
    };

    const int ktmax = 2 * qt + 1;      // >= 1 always
    load_kv(0, 0);
    load_kv(1, 1);

    float O[8][4];
#pragma unroll
    for (int ht = 0; ht < 8; ht++)
#pragma unroll
        for (int j = 0; j < 4; j++) O[ht][j] = 0.f;
    float m0 = -CUDART_INF_F, m1 = -CUDART_INF_F, l0 = 0.f, l1 = 0.f;

    const int qr0 = qt * 128 + wid * 16 + (lane >> 2);
    const int wrow_max = qt * 128 + wid * 16 + 15;   // warp's last q row

    for (int kt = 0; kt <= ktmax; kt++) {
        if (kt + 2 <= ktmax) CP_WAIT1(); else CP_WAIT0();
        __syncthreads();
        if (kt + 2 <= ktmax) load_kv(kt + 2, (kt + 2) % 3);
        const uint32_t kvb = sb + FQARR + (uint32_t)(kt % 3) * FKVSTAGE;

        // Last diagonal tile covers keys >= qt*128+64: warps 0-3 attend
        // nothing there — skip their compute (barriers already done above).
        if (kt == ktmax && wid < 4) continue;

        // ---- scores: S = Q·K^T; skip fully-masked 16-key sub-tiles ----
        float c[8][4];
#pragma unroll
        for (int nt = 0; nt < 8; nt++)
#pragma unroll
            for (int j = 0; j < 4; j++) c[nt][j] = 0.f;

#pragma unroll
        for (int ks = 0; ks < 4; ks++) {
            const uint32_t ch = ks * 2 + lch;
            uint32_t q0, q1, q2, q3;
            uint32_t kf[4][4];
            LDSM_X4(q0, q1, q2, q3, sb + sw128(wid * 16 + lrow, ch));
#pragma unroll
            for (int bp = 0; bp < 4; bp++) {
                if (kt * 64 + bp * 16 > wrow_max) continue;   // warp-uniform
                LDSM_X4(kf[bp][0], kf[bp][1], kf[bp][2], kf[bp][3],
                        kvb + sw128(bp * 16 + lrow, ch));
            }
#pragma unroll
            for (int bp = 0; bp < 4; bp++) {
                if (kt * 64 + bp * 16 > wrow_max) continue;   // warp-uniform
                MMA_F16(c[bp * 2],     q0, q1, q2, q3, kf[bp][0], kf[bp][2]);
                MMA_F16(c[bp * 2 + 1], q0, q1, q2, q3, kf[bp][1], kf[bp][3]);
            }
        }

        // ---- causal mask ----
        if (kt * 64 + 63 > qt * 128 + wid * 16) {
#pragma unroll
            for (int nt = 0; nt < 8; nt++) {
                int kc = kt * 64 + nt * 8 + (lane & 3) * 2;
                if (kc     > qr0)     c[nt][0] = -CUDART_INF_F;
                if (kc + 1 > qr0)     c[nt][1] = -CUDART_INF_F;
                if (kc     > qr0 + 8) c[nt][2] = -CUDART_INF_F;
                if (kc + 1 > qr0 + 8) c[nt][3] = -CUDART_INF_F;
            }
        }

        // ---- online softmax ----
        float mt0 = -CUDART_INF_F, mt1 = -CUDART_INF_F;
#pragma unroll
        for (int nt = 0; nt < 8; nt++) {
            mt0 = fmaxf(mt0, fmaxf(c[nt][0], c[nt][1]));
            mt1 = fmaxf(mt1, fmaxf(c[nt][2], c[nt][3]));
        }
        mt0 = fmaxf(mt0, __shfl_xor_sync(0xffffffffu, mt0, 1));
        mt0 = fmaxf(mt0, __shfl_xor_sync(0xffffffffu, mt0, 2));
        mt1 = fmaxf(mt1, __shfl_xor_sync(0xffffffffu, mt1, 1));
        mt1 = fmaxf(mt1, __shfl_xor_sync(0xffffffffu, mt1, 2));

        float mn0 = fmaxf(m0, mt0), mn1 = fmaxf(m1, mt1);
        float f0 = __expf(m0 - mn0), f1 = __expf(m1 - mn1);
        float s0 = 0.f, s1 = 0.f;
        uint32_t pa0[8], pa1[8];
#pragma unroll
        for (int nt = 0; nt < 8; nt++) {
            float p0 = __expf(c[nt][0] - mn0), p1 = __expf(c[nt][1] - mn0);
            float p2 = __expf(c[nt][2] - mn1), p3 = __expf(c[nt][3] - mn1);
            s0 += p0 + p1; s1 += p2 + p3;
            pa0[nt] = pack_hf2(p0, p1);
            pa1[nt] = pack_hf2(p2, p3);
        }
        s0 += __shfl_xor_sync(0xffffffffu, s0, 1);
        s0 += __shfl_xor_sync(0xffffffffu, s0, 2);
        s1 += __shfl_xor_sync(0xffffffffu, s1, 1);
        s1 += __shfl_xor_sync(0xffffffffu, s1, 2);
        l0 = l0 * f0 + s0;  m0 = mn0;
        l1 = l1 * f1 + s1;  m1 = mn1;
#pragma unroll
        for (int ht = 0; ht < 8; ht++) {
            O[ht][0] *= f0; O[ht][1] *= f0;
            O[ht][2] *= f1; O[ht][3] *= f1;
        }

        // ---- PV: O += P·V; skip key-groups whose P is all zero ----
#pragma unroll
        for (int ksi = 0; ksi < 4; ksi++) {
            if (kt * 64 + ksi * 16 > wrow_max) continue;      // warp-uniform
            uint32_t a0 = pa0[2 * ksi],     a1 = pa1[2 * ksi];
            uint32_t a2 = pa0[2 * ksi + 1], a3 = pa1[2 * ksi + 1];
            uint32_t vf[4][4];
#pragma unroll
            for (int bp = 0; bp < 4; bp++)
                LDSM_X4_T(vf[bp][0], vf[bp][1], vf[bp][2], vf[bp][3],
                          kvb + FKVARR + sw128(ksi * 16 + lrow, bp * 2 + lch));
#pragma unroll
            for (int bp = 0; bp < 2; bp++) {
                MMA_F16(O[bp * 4 + 0], a0, a1, a2, a3, vf[bp * 2][0], vf[bp * 2][1]);
                MMA_F16(O[bp * 4 + 1], a0, a1, a2, a3, vf[bp * 2][2], vf[bp * 2][3]);
                MMA_F16(O[bp * 4 + 2], a0, a1, a2, a3, vf[bp * 2 + 1][0], vf[bp * 2 + 1][1]);
                MMA_F16(O[bp * 4 + 3], a0, a1, a2, a3, vf[bp * 2 + 1][2], vf[bp * 2 + 1][3]);
            }
        }
    }

    // ---- epilogue ----
    float i0 = 1.f / l0, i1 = 1.f / l1;
    size_t r0g = qrowg + wid * 16 + (lane >> 2);
    size_t r1g = r0g + 8;
    int cb = hcol + (lane & 3) * 2;
#pragma unroll
    for (int ht = 0; ht < 8; ht++) {
        int col = cb + ht * 8;
        *(uint32_t*)&oh[r0g * DDIM + col] = pack_hf2(O[ht][0] * i0, O[ht][1] * i0);
        *(uint32_t*)&oh[r1g * DDIM + col] = pack_hf2(O[ht][2] * i1, O[ht][3] * i1);
    }
}

// ---------------------------------------------------------------------------
extern "C" void kernel_launch(void* const* d_in, const int* in_sizes, int n_in,
                              void* d_out, int out_size)
{
    const float* x      = (const float*)d_in[0];
    const float* w_attn = (const float*)d_in[1];
    const float* b_attn = (const float*)d_in[2];
    const float* w_proj = (const float*)d_in[3];
    const float* b_proj = (const float*)d_in[4];
    float* out = (float*)d_out;

    __half *qkv, *xh, *w1h, *w2h, *ah;
    cudaGetSymbolAddress((void**)&qkv, g_qkv);
    cudaGetSymbolAddress((void**)&xh,  g_xh);
    cudaGetSymbolAddress((void**)&w1h, g_w1h);
    cudaGetSymbolAddress((void**)&w2h, g_w2h);
    cudaGetSymbolAddress((void**)&ah,  g_ah);

    cudaFuncSetAttribute(hmma_gemm<0>,
                         cudaFuncAttributeMaxDynamicSharedMemorySize, HMMA_SMEM);
    cudaFuncSetAttribute(hmma_gemm<1>,
                         cudaFuncAttributeMaxDynamicSharedMemorySize, HMMA_SMEM);
    cudaFuncSetAttribute(flash_hmma,
                         cudaFuncAttributeMaxDynamicSharedMemorySize, FL_SMEM);

    // Prep (single fused launch: x cast + both weight transposes)
    prep_all<<<5120, 256>>>(x, xh, w_attn, w1h, w_proj, w2h);

    // 1) QKV (fp16 out, Q pre-scaled)
    hmma_gemm<1><<<dim3(QKV_LD / 128, MM / 128), 256, HMMA_SMEM>>>(
        xh, w1h, b_attn, nullptr, qkv, DDIM, QKV_LD);

    // 2) flash attention (1-D LPT grid) -> fp16 attention output
    flash_hmma<<<NQT * HH * BB, 256, FL_SMEM>>>(qkv, ah);

    // 3) proj (fp32 out)
    hmma_gemm<0><<<dim3(DDIM / 128, MM / 128), 256, HMMA_SMEM>>>(
        ah, w2h, b_proj, out, nullptr, DDIM, DDIM);
}

// round 16
// speedup vs baseline: 1.7225x; 1.0215x over previous
#include <cuda_runtime.h>
#include <cuda_fp16.h>
#include <math_constants.h>
#include <cstdint>

#define BB 2
#define SS 2048
#define DDIM 1024
#define HH 16
#define HDIM 64
#define MM (BB*SS)          // 4096 rows
#define QKV_LD 3072         // 3*D
#define NQT (SS/128)        // 16 q-tiles

// ---------------------------------------------------------------------------
// Scratch (device globals: allowed; runtime allocs are not)
// ---------------------------------------------------------------------------
__device__ __half g_qkv[(size_t)MM * QKV_LD];    // QKV fp16 (Q pre-scaled, base-2 domain)
__device__ __half g_xh[(size_t)MM * DDIM];       // x fp16
__device__ __half g_w1h[(size_t)QKV_LD * DDIM];  // w_attn^T fp16 [3072,1024]
__device__ __half g_w2h[(size_t)DDIM * DDIM];    // w_proj^T fp16 [1024,1024]
__device__ __half g_ah[(size_t)MM * DDIM];       // attention out fp16

// ---------------------------------------------------------------------------
// Portable PTX helpers
// ---------------------------------------------------------------------------
__device__ __forceinline__ uint32_t smem_u32(const void* p) {
    uint32_t a;
    asm("{ .reg .u64 t; cvta.to.shared.u64 t, %1; cvt.u32.u64 %0, t; }"
        : "=r"(a) : "l"(p));
    return a;
}

#define CP_ASYNC16(sa, gp) \
    asm volatile("cp.async.cg.shared.global [%0], [%1], 16;" :: "r"(sa), "l"(gp))
#define CP_COMMIT() asm volatile("cp.async.commit_group;" ::: "memory")
#define CP_WAIT1()  asm volatile("cp.async.wait_group 1;" ::: "memory")
#define CP_WAIT0()  asm volatile("cp.async.wait_group 0;" ::: "memory")

#define LDSM_X4(r0, r1, r2, r3, addr) \
    asm volatile("ldmatrix.sync.aligned.m8n8.x4.shared.b16 {%0,%1,%2,%3}, [%4];" \
        : "=r"(r0), "=r"(r1), "=r"(r2), "=r"(r3) : "r"(addr))

#define LDSM_X4_T(r0, r1, r2, r3, addr) \
    asm volatile("ldmatrix.sync.aligned.m8n8.x4.trans.shared.b16 {%0,%1,%2,%3}, [%4];" \
        : "=r"(r0), "=r"(r1), "=r"(r2), "=r"(r3) : "r"(addr))

#define MMA_F16(c, a0, a1, a2, a3, b0, b1) \
    asm volatile("mma.sync.aligned.m16n8k16.row.col.f32.f16.f16.f32 " \
        "{%0,%1,%2,%3}, {%4,%5,%6,%7}, {%8,%9}, {%0,%1,%2,%3};" \
        : "+f"((c)[0]), "+f"((c)[1]), "+f"((c)[2]), "+f"((c)[3]) \
        : "r"(a0), "r"(a1), "r"(a2), "r"(a3), "r"(b0), "r"(b1))

__device__ __forceinline__ uint32_t pack_hf2(float a, float b) {
    __half2 t = __floats2half2_rn(a, b);
    return *(uint32_t*)&t;
}
__device__ __forceinline__ float ex2f(float x) {
    float r;
    asm("ex2.approx.f32 %0, %1;" : "=f"(r) : "f"(x));
    return r;
}
__device__ __forceinline__ uint32_t ex2_h2(uint32_t a) {
    uint32_t r;
    asm("ex2.approx.f16x2 %0, %1;" : "=r"(r) : "r"(a));
    return r;
}

// XOR swizzle for 128B rows (ch in 0..7): conflict-free per 8-lane phase.
__device__ __forceinline__ uint32_t sw128(uint32_t r, uint32_t ch) {
    return r * 128 + ((ch ^ (r & 7)) << 4);
}

// ---------------------------------------------------------------------------
// Fused prep: one launch does x->fp16 cast + both weight transposes.
// ---------------------------------------------------------------------------
__device__ __forceinline__ void transpose_body(const float* __restrict__ W,
                                               __half* __restrict__ hi,
                                               int K, int N, int bx, int by,
                                               int tid)
{
    __shared__ float t[32][33];
    int n0 = bx * 32, k0 = by * 32;
    int tx = tid & 31, ty = tid >> 5;
#pragma unroll
    for (int i = 0; i < 32; i += 8)
        t[ty + i][tx] = W[(size_t)(k0 + ty + i) * N + n0 + tx];
    __syncthreads();
#pragma unroll
    for (int i = 0; i < 32; i += 8)
        hi[(size_t)(n0 + ty + i) * K + k0 + tx] = __float2half(t[tx][ty + i]);
}

__global__ void prep_all(const float* __restrict__ x, __half* __restrict__ xh,
                         const float* __restrict__ w1, __half* __restrict__ w1h,
                         const float* __restrict__ w2, __half* __restrict__ w2h)
{
    const int bid = blockIdx.x, tid = threadIdx.x;
    if (bid < 1024) {
        const int n4 = MM * DDIM / 4;
        for (int i = bid * 256 + tid; i < n4; i += 1024 * 256) {
            float4 v = ((const float4*)x)[i];
            ((uint32_t*)xh)[2 * i]     = pack_hf2(v.x, v.y);
            ((uint32_t*)xh)[2 * i + 1] = pack_hf2(v.z, v.w);
        }
    } else if (bid < 4096) {
        int t = bid - 1024;                       // 96 x 32 blocks
        transpose_body(w1, w1h, DDIM, QKV_LD, t % 96, t / 96, tid);
    } else {
        int t = bid - 4096;                       // 32 x 32 blocks
        transpose_body(w2, w2h, DDIM, DDIM, t % 32, t / 32, tid);
    }
}

// ---------------------------------------------------------------------------
// HMMA fp16 GEMM + bias (fp32 accumulate): C = Ah @ Bh^T + bias
// 128x128 CTA, 32x64 warp tile, K-tile 64, 3-stage cp.async, reg double-buf.
// MODE 0: fp32 C.  MODE 1: fp16 C (Q cols scaled by log2e/8 -> base-2 scores).
// ---------------------------------------------------------------------------
#define GARR 16384
#define GSTAGE (2 * GARR)            // 32768
#define HMMA_SMEM (3 * GSTAGE)       // 98304 -> 2 CTAs/SM
#define QSCALE 0.1803368801f         // 0.125 * log2(e)

template<int MODE>
__global__ __launch_bounds__(256, 2)
void hmma_gemm(const __half* __restrict__ Ah, const __half* __restrict__ Bh,
               const float* __restrict__ bias, float* __restrict__ C,
               __half* __restrict__ Chi, int K, int N)
{
    extern __shared__ __align__(16) char smraw[];
    const uint32_t sb = smem_u32(smraw);

    const int tid = threadIdx.x;
    const int wid = tid >> 5, lane = tid & 31;
    const int m0 = blockIdx.y * 128, n0 = blockIdx.x * 128;
    const int warp_m = wid & 3;
    const int warp_n = wid >> 2;

    float c[2][8][4];
#pragma unroll
    for (int mi = 0; mi < 2; mi++)
#pragma unroll
        for (int nt = 0; nt < 8; nt++)
#pragma unroll
            for (int j = 0; j < 4; j++) c[mi][nt][j] = 0.f;

    const int nkt = K / 64;

    auto load_stage = [&](int kt, int slot) {
        const int k0 = kt * 64;
        const uint32_t sbase = sb + (uint32_t)slot * GSTAGE;
#pragma unroll
        for (int arr = 0; arr < 2; arr++) {
            const __half* P = (arr == 0) ? Ah : Bh;
            const int rowbase = (arr == 0) ? m0 : n0;
#pragma unroll
            for (int i = 0; i < 4; i++) {
                uint32_t idx = tid + i * 256;
                uint32_t r = idx >> 3, ch = idx & 7;
                const __half* gp = P + (size_t)(rowbase + r) * K + k0 + ch * 8;
                CP_ASYNC16(sbase + arr * GARR + sw128(r, ch), gp);
            }
        }
        CP_COMMIT();
    };

    load_stage(0, 0);
    load_stage(1, 1);

    const uint32_t lrow = lane & 15;
    const uint32_t lch  = lane >> 4;
    const uint32_t aRow = (uint32_t)(warp_m * 32) + lrow;
    const uint32_t bRow = (uint32_t)(warp_n * 64) + lrow;

    for (int kt = 0; kt < nkt; kt++) {
        if (kt + 2 < nkt) CP_WAIT1(); else CP_WAIT0();
        __syncthreads();
        if (kt + 2 < nkt) load_stage(kt + 2, (kt + 2) % 3);

        const uint32_t sbase = sb + (uint32_t)(kt % 3) * GSTAGE;

        uint32_t ah[2][2][4];   // [buf][mi][frag]
        uint32_t bh[2][4];      // [buf][frag]

        {
            const uint32_t ch = lch;
            LDSM_X4(ah[0][0][0], ah[0][0][1], ah[0][0][2], ah[0][0][3],
                    sbase + sw128(aRow, ch));
            LDSM_X4(ah[0][1][0], ah[0][1][1], ah[0][1][2], ah[0][1][3],
                    sbase + sw128(aRow + 16, ch));
            LDSM_X4(bh[0][0], bh[0][1], bh[0][2], bh[0][3],
                    sbase + GARR + sw128(bRow, ch));
        }

#pragma unroll
        for (int ks = 0; ks < 4; ks++) {
            const int ab = ks & 1;
#pragma unroll
            for (int np = 0; np < 4; np++) {
                const int bb = np & 1;
                if (np < 3) {
                    const uint32_t ch = ks * 2 + lch;
                    LDSM_X4(bh[bb ^ 1][0], bh[bb ^ 1][1], bh[bb ^ 1][2], bh[bb ^ 1][3],
                            sbase + GARR + sw128(bRow + (np + 1) * 16, ch));
                } else if (ks < 3) {
                    const uint32_t ch = (ks + 1) * 2 + lch;
                    LDSM_X4(ah[ab ^ 1][0][0], ah[ab ^ 1][0][1], ah[ab ^ 1][0][2], ah[ab ^ 1][0][3],
                            sbase + sw128(aRow, ch));
                    LDSM_X4(ah[ab ^ 1][1][0], ah[ab ^ 1][1][1], ah[ab ^ 1][1][2], ah[ab ^ 1][1][3],
                            sbase + sw128(aRow + 16, ch));
                    LDSM_X4(bh[bb ^ 1][0], bh[bb ^ 1][1], bh[bb ^ 1][2], bh[bb ^ 1][3],
                            sbase + GARR + sw128(bRow, ch));
                }
                const int n0t = np * 2, n1t = np * 2 + 1;
                MMA_F16(c[0][n0t], ah[ab][0][0], ah[ab][0][1], ah[ab][0][2], ah[ab][0][3],
                        bh[bb][0], bh[bb][2]);
                MMA_F16(c[0][n1t], ah[ab][0][0], ah[ab][0][1], ah[ab][0][2], ah[ab][0][3],
                        bh[bb][1], bh[bb][3]);
                MMA_F16(c[1][n0t], ah[ab][1][0], ah[ab][1][1], ah[ab][1][2], ah[ab][1][3],
                        bh[bb][0], bh[bb][2]);
                MMA_F16(c[1][n1t], ah[ab][1][0], ah[ab][1][1], ah[ab][1][2], ah[ab][1][3],
                        bh[bb][1], bh[bb][3]);
            }
        }
    }

    // Epilogue
#pragma unroll
    for (int mi = 0; mi < 2; mi++) {
        int r0 = m0 + warp_m * 32 + mi * 16 + (lane >> 2);
        int r1 = r0 + 8;
#pragma unroll
        for (int nt = 0; nt < 8; nt++) {
            int col = n0 + warp_n * 64 + nt * 8 + (lane & 3) * 2;
            float b0 = bias[col], b1 = bias[col + 1];
            float v00 = c[mi][nt][0] + b0, v01 = c[mi][nt][1] + b1;
            float v10 = c[mi][nt][2] + b0, v11 = c[mi][nt][3] + b1;
            if (MODE == 0) {
                *(float2*)&C[(size_t)r0 * N + col] = make_float2(v00, v01);
                *(float2*)&C[(size_t)r1 * N + col] = make_float2(v10, v11);
            } else {
                if (col < DDIM) {   // Q columns: fold (1/sqrt(hd))*log2(e)
                    v00 *= QSCALE; v01 *= QSCALE; v10 *= QSCALE; v11 *= QSCALE;
                }
                *(uint32_t*)&Chi[(size_t)r0 * N + col] = pack_hf2(v00, v01);
                *(uint32_t*)&Chi[(size_t)r1 * N + col] = pack_hf2(v10, v11);
            }
        }
    }
}

// ---------------------------------------------------------------------------
// HMMA flash attention, causal, fp16 (fp32 accumulate).
// 1-D LPT grid, 3-stage KV pipeline, masked-warp/sub-tile skips.
// Softmax in base-2 domain: P computed with ex2.approx.f16x2.
// ---------------------------------------------------------------------------
#define FQARR (128 * 128)
#define FKVARR (64 * 128)
#define FKVSTAGE (2 * FKVARR)            // Kh, Vh = 16384
#define FL_SMEM (FQARR + 3 * FKVSTAGE)   // 65536 bytes

__global__ __launch_bounds__(256, 2)
void flash_hmma(const __half* __restrict__ qkv, __half* __restrict__ oh)
{
    extern __shared__ __align__(16) char smraw[];
    const uint32_t sb = smem_u32(smraw);
    const int tid = threadIdx.x, wid = tid >> 5, lane = tid & 31;
    const int bid = blockIdx.x;
    const int qt = (NQT - 1) - (bid >> 5);    // LPT: qt descending
    const int hb = bid & 31;
    const int h = hb >> 1, b = hb & 1;
    const size_t qrowg = (size_t)(b * SS + qt * 128);
    const int hcol = h * HDIM;
    const uint32_t lrow = lane & 15, lch = lane >> 4;

    // Q -> smem (group 0)
#pragma unroll
    for (int i = 0; i < 4; i++) {
        uint32_t idx = tid + i * 256;
        uint32_t r = idx >> 3, ch = idx & 7;
        size_t g = (qrowg + r) * QKV_LD + hcol + ch * 8;
        CP_ASYNC16(sb + sw128(r, ch), qkv + g);
    }
    CP_COMMIT();

    auto load_kv = [&](int kt, int s) {
        size_t krow = (size_t)(b * SS + kt * 64);
        uint32_t sbase = sb + FQARR + (uint32_t)s * FKVSTAGE;
#pragma unroll
        for (int i = 0; i < 2; i++) {
            uint32_t idx = tid + i * 256;
            uint32_t r = idx >> 3, ch = idx & 7;
            size_t g = (krow + r) * QKV_LD + DDIM + hcol + ch * 8;
            uint32_t so = sw128(r, ch);
            CP_ASYNC16(sbase + so,          qkv + g);          // K
            CP_ASYNC16(sbase + FKVARR + so, qkv + g + DDIM);   // V
        }
        CP_COMMIT();
    };

    const int ktmax = 2 * qt + 1;      // >= 1 always
    load_kv(0, 0);
    load_kv(1, 1);

    float O[8][4];
#pragma unroll
    for (int ht = 0; ht < 8; ht++)
#pragma unroll
        for (int j = 0; j < 4; j++) O[ht][j] = 0.f;
    float m0 = -CUDART_INF_F, m1 = -CUDART_INF_F, l0 = 0.f, l1 = 0.f;

    const int qr0 = qt * 128 + wid * 16 + (lane >> 2);
    const int wrow_max = qt * 128 + wid * 16 + 15;   // warp's last q row

    for (int kt = 0; kt <= ktmax; kt++) {
        if (kt + 2 <= ktmax) CP_WAIT1(); else CP_WAIT0();
        __syncthreads();
        if (kt + 2 <= ktmax) load_kv(kt + 2, (kt + 2) % 3);
        const uint32_t kvb = sb + FQARR + (uint32_t)(kt % 3) * FKVSTAGE;

        if (kt == ktmax && wid < 4) continue;   // fully-masked warps

        // ---- scores: S = Q·K^T (base-2 domain); skip masked sub-tiles ----
        float c[8][4];
#pragma unroll
        for (int nt = 0; nt < 8; nt++)
#pragma unroll
            for (int j = 0; j < 4; j++) c[nt][j] = 0.f;

#pragma unroll
        for (int ks = 0; ks < 4; ks++) {
            const uint32_t ch = ks * 2 + lch;
            uint32_t q0, q1, q2, q3;
            uint32_t kf[4][4];
            LDSM_X4(q0, q1, q2, q3, sb + sw128(wid * 16 + lrow, ch));
#pragma unroll
            for (int bp = 0; bp < 4; bp++) {
                if (kt * 64 + bp * 16 > wrow_max) continue;   // warp-uniform
                LDSM_X4(kf[bp][0], kf[bp][1], kf[bp][2], kf[bp][3],
                        kvb + sw128(bp * 16 + lrow, ch));
            }
#pragma unroll
            for (int bp = 0; bp < 4; bp++) {
                if (kt * 64 + bp * 16 > wrow_max) continue;   // warp-uniform
                MMA_F16(c[bp * 2],     q0, q1, q2, q3, kf[bp][0], kf[bp][2]);
                MMA_F16(c[bp * 2 + 1], q0, q1, q2, q3, kf[bp][1], kf[bp][3]);
            }
        }

        // ---- causal mask ----
        if (kt * 64 + 63 > qt * 128 + wid * 16) {
#pragma unroll
            for (int nt = 0; nt < 8; nt++) {
                int kc = kt * 64 + nt * 8 + (lane & 3) * 2;
                if (kc     > qr0)     c[nt][0] = -CUDART_INF_F;
                if (kc + 1 > qr0)     c[nt][1] = -CUDART_INF_F;
                if (kc     > qr0 + 8) c[nt][2] = -CUDART_INF_F;
                if (kc + 1 > qr0 + 8) c[nt][3] = -CUDART_INF_F;
            }
        }

        // ---- online softmax (base-2; P via ex2.approx.f16x2) ----
        float mt0 = -CUDART_INF_F, mt1 = -CUDART_INF_F;
#pragma unroll
        for (int nt = 0; nt < 8; nt++) {
            mt0 = fmaxf(mt0, fmaxf(c[nt][0], c[nt][1]));
            mt1 = fmaxf(mt1, fmaxf(c[nt][2], c[nt][3]));
        }
        mt0 = fmaxf(mt0, __shfl_xor_sync(0xffffffffu, mt0, 1));
        mt0 = fmaxf(mt0, __shfl_xor_sync(0xffffffffu, mt0, 2));
        mt1 = fmaxf(mt1, __shfl_xor_sync(0xffffffffu, mt1, 1));
        mt1 = fmaxf(mt1, __shfl_xor_sync(0xffffffffu, mt1, 2));

        float mn0 = fmaxf(m0, mt0), mn1 = fmaxf(m1, mt1);
        float f0 = ex2f(m0 - mn0), f1 = ex2f(m1 - mn1);
        float s0 = 0.f, s1 = 0.f;
        uint32_t pa0[8], pa1[8];
#pragma unroll
        for (int nt = 0; nt < 8; nt++) {
            pa0[nt] = ex2_h2(pack_hf2(c[nt][0] - mn0, c[nt][1] - mn0));
            pa1[nt] = ex2_h2(pack_hf2(c[nt][2] - mn1, c[nt][3] - mn1));
            float2 u0 = __half22float2(*(__half2*)&pa0[nt]);
            float2 u1 = __half22float2(*(__half2*)&pa1[nt]);
            s0 += u0.x + u0.y;
            s1 += u1.x + u1.y;
        }
        s0 += __shfl_xor_sync(0xffffffffu, s0, 1);
        s0 += __shfl_xor_sync(0xffffffffu, s0, 2);
        s1 += __shfl_xor_sync(0xffffffffu, s1, 1);
        s1 += __shfl_xor_sync(0xffffffffu, s1, 2);
        l0 = l0 * f0 + s0;  m0 = mn0;
        l1 = l1 * f1 + s1;  m1 = mn1;
#pragma unroll
        for (int ht = 0; ht < 8; ht++) {
            O[ht][0] *= f0; O[ht][1] *= f0;
            O[ht][2] *= f1; O[ht][3] *= f1;
        }

        // ---- PV: O += P·V; skip key-groups whose P is all zero ----
#pragma unroll
        for (int ksi = 0; ksi < 4; ksi++) {
            if (kt * 64 + ksi * 16 > wrow_max) continue;      // warp-uniform
            uint32_t a0 = pa0[2 * ksi],     a1 = pa1[2 * ksi];
            uint32_t a2 = pa0[2 * ksi + 1], a3 = pa1[2 * ksi + 1];
            uint32_t vf[4][4];
#pragma unroll
            for (int bp = 0; bp < 4; bp++)
                LDSM_X4_T(vf[bp][0], vf[bp][1], vf[bp][2], vf[bp][3],
                          kvb + FKVARR + sw128(ksi * 16 + lrow, bp * 2 + lch));
#pragma unroll
            for (int bp = 0; bp < 2; bp++) {
                MMA_F16(O[bp * 4 + 0], a0, a1, a2, a3, vf[bp * 2][0], vf[bp * 2][1]);
                MMA_F16(O[bp * 4 + 1], a0, a1, a2, a3, vf[bp * 2][2], vf[bp * 2][3]);
                MMA_F16(O[bp * 4 + 2], a0, a1, a2, a3, vf[bp * 2 + 1][0], vf[bp * 2 + 1][1]);
                MMA_F16(O[bp * 4 + 3], a0, a1, a2, a3, vf[bp * 2 + 1][2], vf[bp * 2 + 1][3]);
            }
        }
    }

    // ---- epilogue ----
    float i0 = 1.f / l0, i1 = 1.f / l1;
    size_t r0g = qrowg + wid * 16 + (lane >> 2);
    size_t r1g = r0g + 8;
    int cb = hcol + (lane & 3) * 2;
#pragma unroll
    for (int ht = 0; ht < 8; ht++) {
        int col = cb + ht * 8;
        *(uint32_t*)&oh[r0g * DDIM + col] = pack_hf2(O[ht][0] * i0, O[ht][1] * i0);
        *(uint32_t*)&oh[r1g * DDIM + col] = pack_hf2(O[ht][2] * i1, O[ht][3] * i1);
    }
}

// ---------------------------------------------------------------------------
extern "C" void kernel_launch(void* const* d_in, const int* in_sizes, int n_in,
                              void* d_out, int out_size)
{
    const float* x      = (const float*)d_in[0];
    const float* w_attn = (const float*)d_in[1];
    const float* b_attn = (const float*)d_in[2];
    const float* w_proj = (const float*)d_in[3];
    const float* b_proj = (const float*)d_in[4];
    float* out = (float*)d_out;

    __half *qkv, *xh, *w1h, *w2h, *ah;
    cudaGetSymbolAddress((void**)&qkv, g_qkv);
    cudaGetSymbolAddress((void**)&xh,  g_xh);
    cudaGetSymbolAddress((void**)&w1h, g_w1h);
    cudaGetSymbolAddress((void**)&w2h, g_w2h);
    cudaGetSymbolAddress((void**)&ah,  g_ah);

    cudaFuncSetAttribute(hmma_gemm<0>,
                         cudaFuncAttributeMaxDynamicSharedMemorySize, HMMA_SMEM);
    cudaFuncSetAttribute(hmma_gemm<1>,
                         cudaFuncAttributeMaxDynamicSharedMemorySize, HMMA_SMEM);
    cudaFuncSetAttribute(flash_hmma,
                         cudaFuncAttributeMaxDynamicSharedMemorySize, FL_SMEM);

    // Prep (single fused launch: x cast + both weight transposes)
    prep_all<<<5120, 256>>>(x, xh, w_attn, w1h, w_proj, w2h);

    // 1) QKV (fp16 out, Q pre-scaled into base-2 domain)
    hmma_gemm<1><<<dim3(QKV_LD / 128, MM / 128), 256, HMMA_SMEM>>>(
        xh, w1h, b_attn, nullptr, qkv, DDIM, QKV_LD);

    // 2) flash attention (1-D LPT grid) -> fp16 attention output
    flash_hmma<<<NQT * HH * BB, 256, FL_SMEM>>>(qkv, ah);

    // 3) proj (fp32 out)
    hmma_gemm<0><<<dim3(DDIM / 128, MM / 128), 256, HMMA_SMEM>>>(
        ah, w2h, b_proj, out, nullptr, DDIM, DDIM);
}